// round 8
// baseline (speedup 1.0000x reference)
#include <cuda_runtime.h>
#include <math.h>

// Problem constants
#define BSZ 128
#define SSZ 256
#define ESZ 300
#define HSZ 512
#define G4  2048           // 4*H
#define NB_RECUR 128       // persistent kernel grid (<= 148 SMs -> co-resident wave 1)

// ---------------- scratch (static device memory; no runtime allocation) -----
// PRE1 (layer-1 pre-activations) aliases PRE0F: layer-0 fwd pre-activations are
// fully consumed by the layer-0 recurrence before the layer-1 projection runs.
__device__ float PRE0F[SSZ * BSZ * G4];          // [t][b][4H] l0 fwd  (later: l1 rev)
__device__ float PRE0R[SSZ * BSZ * G4];          // [t][b][4H] l0 rev
__device__ float OUT0 [SSZ * BSZ * 2 * HSZ];     // [t][b][2H] concat(fwd,rev)
__device__ float HBUF [9][BSZ * HSZ];
//  0,1: l0f h double-buffer   2: l0f c
//  3,4: l0r h                 5: l0r c
//  6,7: l1r h                 8: l1r c
__device__ int   LEN[BSZ];
__device__ unsigned int BAR_CNT;
__device__ volatile unsigned int BAR_GEN;

__device__ __forceinline__ float sigm(float x) { return 1.0f / (1.0f + expf(-x)); }

// ---------------- init: lengths, ones-init states, barrier reset ------------
__global__ void k_init(const float* __restrict__ x) {
    int tid = blockIdx.x * blockDim.x + threadIdx.x;
    const int slab = BSZ * HSZ;                   // 65536
    // ones-init the 6 "read-first" buffers: 0,2,3,5,6,8
    if (tid < 6 * slab) {
        int w = tid / slab, i = tid - w * slab;
        int buf = (w == 0) ? 0 : (w == 1) ? 2 : (w == 2) ? 3 : (w == 3) ? 5 : (w == 4) ? 6 : 8;
        HBUF[buf][i] = 1.0f;
    }
    if (tid < BSZ) {
        int v = (int)x[((size_t)tid * SSZ + (SSZ - 1)) * ESZ];  // x[b, S-1, 0]
        LEN[tid] = v < SSZ ? v : SSZ;
    }
    if (tid == 0) { BAR_CNT = 0; BAR_GEN = 0; }
}

__global__ void k_reset() { BAR_CNT = 0; BAR_GEN = 0; }

// ---------------- big NT-GEMM: C = A[M,K] * W[2048,K]^T + b1 + b2 -----------
// 128x128 block tile, 8x8 per-thread microtile, KC=8.
// permute==1: output row = (m%256)*128 + (m/256)   (b*S+t row -> [t][b] layout)
// permute==0: output row = m
__global__ void __launch_bounds__(256, 1) k_gemm(
    const float* __restrict__ A, int M, int K,
    const float* __restrict__ W,
    const float* __restrict__ b1, const float* __restrict__ b2,
    float* __restrict__ C, int permute)
{
    __shared__ float As[8][128];
    __shared__ float Bs[8][128];

    int tid = threadIdx.x;
    int ty = tid >> 4, tx = tid & 15;
    int mbase = blockIdx.y * 128;
    int nbase = blockIdx.x * 128;

    float acc[8][8];
#pragma unroll
    for (int i = 0; i < 8; i++)
#pragma unroll
        for (int j = 0; j < 8; j++) acc[i][j] = 0.0f;

    int lrow = tid >> 1;            // 0..127
    int lk   = (tid & 1) * 4;       // 0 or 4
    const float* Arow = A + (size_t)(mbase + lrow) * K;
    const float* Wrow = W + (size_t)(nbase + lrow) * K;

    for (int kb = 0; kb < K; kb += 8) {
        float av[4], wv[4];
        if (kb + lk + 3 < K) {
            float4 t = *(const float4*)(Arow + kb + lk);
            av[0] = t.x; av[1] = t.y; av[2] = t.z; av[3] = t.w;
            float4 u = *(const float4*)(Wrow + kb + lk);
            wv[0] = u.x; wv[1] = u.y; wv[2] = u.z; wv[3] = u.w;
        } else {
#pragma unroll
            for (int i = 0; i < 4; i++) {
                int k = kb + lk + i;
                av[i] = (k < K) ? Arow[k] : 0.0f;
                wv[i] = (k < K) ? Wrow[k] : 0.0f;
            }
        }
        __syncthreads();
#pragma unroll
        for (int i = 0; i < 4; i++) {
            As[lk + i][lrow] = av[i];
            Bs[lk + i][lrow] = wv[i];
        }
        __syncthreads();
#pragma unroll
        for (int kk = 0; kk < 8; kk++) {
            float a[8], b[8];
            *(float4*)&a[0] = *(const float4*)&As[kk][ty * 8];
            *(float4*)&a[4] = *(const float4*)&As[kk][ty * 8 + 4];
            *(float4*)&b[0] = *(const float4*)&Bs[kk][tx * 8];
            *(float4*)&b[4] = *(const float4*)&Bs[kk][tx * 8 + 4];
#pragma unroll
            for (int i = 0; i < 8; i++)
#pragma unroll
                for (int j = 0; j < 8; j++) acc[i][j] += a[i] * b[j];
        }
    }

    // store with bias
#pragma unroll
    for (int i = 0; i < 8; i++) {
        int m = mbase + ty * 8 + i;
        int crow = permute ? (((m & 255) << 7) + (m >> 8)) : m;
        float* Cr = C + (size_t)crow * G4 + nbase + tx * 8;
        const float* p1 = b1 + nbase + tx * 8;
        const float* p2 = b2 + nbase + tx * 8;
#pragma unroll
        for (int j = 0; j < 8; j++) Cr[j] = acc[i][j] + p1[j] + p2[j];
    }
}

// ---------------- persistent recurrence kernel ------------------------------
struct RP {
    const float* pre0; const float* whh0;
    float* h0a; float* h0b; float* c0; float* out0; int rev0;
    const float* pre1; const float* whh1;
    float* h1a; float* h1b; float* c1; float* out1; int rev1;
    int ndirs;
};

__device__ __forceinline__ void gsync(unsigned int& lg) {
    __syncthreads();
    if (threadIdx.x == 0) {
        __threadfence();
        unsigned int target = lg + 1;
        if (atomicAdd(&BAR_CNT, 1u) == (unsigned)(NB_RECUR - 1)) {
            atomicExch(&BAR_CNT, 0u);
            __threadfence();
            BAR_GEN = target;
        } else {
            while (BAR_GEN < target) __nanosleep(64);
        }
    }
    lg++;
    __syncthreads();
}

// Tile = 32 batch-rows x (4 gates x 16 hidden cols).  128 tiles per direction.
// One grid_sync per timestep; h double-buffered to avoid intra-step races.
__global__ void __launch_bounds__(256, 1) k_recur(RP p) {
    __shared__ float As[16][32];
    __shared__ float Bs[16][64];
    __shared__ float Zs[32][68];

    int tid = threadIdx.x;
    int ty = tid >> 4, tx = tid & 15;
    int r = ty * 2, cc = tx * 4;
    int aty = tid >> 3;            // A-load: row 0..31
    int akk = (tid & 7) * 2;       // A-load: k pair
    int bn  = tid >> 2;            // B-load: local col 0..63
    int bkk = (tid & 3) * 4;       // B-load: k quad

    unsigned int lg = 0;
    int ntiles = p.ndirs * 128;

    for (int s = 0; s < SSZ; s++) {
        for (int tile = blockIdx.x; tile < ntiles; tile += NB_RECUR) {
            int d   = tile >> 7;
            int sub = tile & 127;
            int rb  = (sub >> 5) * 32;        // batch-row base
            int j0  = (sub & 31) * 16;        // hidden-col base

            const float* pre = d ? p.pre1 : p.pre0;
            const float* whh = d ? p.whh1 : p.whh0;
            float* ha = d ? p.h1a : p.h0a;
            float* hb = d ? p.h1b : p.h0b;
            float* hin  = (s & 1) ? hb : ha;
            float* hout = (s & 1) ? ha : hb;
            float* cst  = d ? p.c1 : p.c0;
            float* outp = d ? p.out1 : p.out0;
            int rev = d ? p.rev1 : p.rev0;
            int tt = rev ? (SSZ - 1 - s) : s;

            // ---- GEMM: Z[32][64] = hin[rb..rb+31][:] * Whh(4 gate-row groups)^T
            float acc[2][4] = {{0, 0, 0, 0}, {0, 0, 0, 0}};
            int wrow = (bn >> 4) * HSZ + j0 + (bn & 15);    // gate*512 + j
            const float* hrow = hin + (size_t)(rb + aty) * HSZ;
            const float* wr   = whh + (size_t)wrow * HSZ;

            for (int kb = 0; kb < HSZ; kb += 16) {
                float2 av = *(const float2*)(hrow + kb + akk);
                float4 wv = *(const float4*)(wr + kb + bkk);
                __syncthreads();
                As[akk][aty] = av.x; As[akk + 1][aty] = av.y;
                Bs[bkk][bn] = wv.x; Bs[bkk + 1][bn] = wv.y;
                Bs[bkk + 2][bn] = wv.z; Bs[bkk + 3][bn] = wv.w;
                __syncthreads();
#pragma unroll
                for (int kk = 0; kk < 16; kk++) {
                    float2 a = *(const float2*)&As[kk][r];
                    float4 b = *(const float4*)&Bs[kk][cc];
                    acc[0][0] += a.x * b.x; acc[0][1] += a.x * b.y;
                    acc[0][2] += a.x * b.z; acc[0][3] += a.x * b.w;
                    acc[1][0] += a.y * b.x; acc[1][1] += a.y * b.y;
                    acc[1][2] += a.y * b.z; acc[1][3] += a.y * b.w;
                }
            }
            // write Z tile to smem (own cells only, then sync)
            *(float4*)&Zs[r][cc]     = *(float4*)&acc[0][0];
            *(float4*)&Zs[r + 1][cc] = *(float4*)&acc[1][0];
            __syncthreads();

            // ---- gates: 512 cells, 2 per thread
#pragma unroll
            for (int q = 0; q < 2; q++) {
                int idx = tid * 2 + q;
                int row = idx >> 4;
                int jj  = idx & 15;
                int brow = rb + row;
                int jg = j0 + jj;
                const float* pb = pre + ((size_t)tt * BSZ + brow) * G4;
                float zi = Zs[row][jj]      + pb[jg];
                float zf = Zs[row][16 + jj] + pb[512 + jg];
                float zg = Zs[row][32 + jj] + pb[1024 + jg];
                float zo = Zs[row][48 + jj] + pb[1536 + jg];
                size_t hidx = (size_t)brow * HSZ + jg;
                float cold = cst[hidx];
                float cn = sigm(zf) * cold + sigm(zi) * tanhf(zg);
                float hn = sigm(zo) * tanhf(cn);
                float hv;
                if (tt < LEN[brow]) { cst[hidx] = cn; hv = hn; }
                else                { hv = hin[hidx]; }
                hout[hidx] = hv;
                if (outp) outp[((size_t)tt * BSZ + brow) * (2 * HSZ) + jg] = hv;
            }
            __syncthreads();
        }
        gsync(lg);   // all h-writes of step s visible before step s+1 reads
    }
}

// ---------------- final FC head: out = (h@fc1^T + b1) @ fc^T + b ------------
__global__ void k_fc(const float* __restrict__ h,
                     const float* __restrict__ fc1w, const float* __restrict__ fc1b,
                     const float* __restrict__ fcw,  const float* __restrict__ fcb,
                     float* __restrict__ out)
{
    __shared__ float tmp[HSZ];
    __shared__ float red[2][256];
    int b = blockIdx.x, tid = threadIdx.x;
    const float* hb = h + (size_t)b * HSZ;

    for (int j = tid; j < HSZ; j += 256) {
        const float* w = fc1w + (size_t)j * HSZ;
        float s0 = 0.f, s1 = 0.f, s2 = 0.f, s3 = 0.f;
        for (int k = 0; k < HSZ; k += 4) {
            s0 += hb[k] * w[k];     s1 += hb[k + 1] * w[k + 1];
            s2 += hb[k + 2] * w[k + 2]; s3 += hb[k + 3] * w[k + 3];
        }
        tmp[j] = s0 + s1 + s2 + s3 + fc1b[j];
    }
    __syncthreads();
    float p0 = 0.f, p1 = 0.f;
    for (int k = tid; k < HSZ; k += 256) {
        p0 += tmp[k] * fcw[k];
        p1 += tmp[k] * fcw[HSZ + k];
    }
    red[0][tid] = p0; red[1][tid] = p1;
    __syncthreads();
    for (int off = 128; off > 0; off >>= 1) {
        if (tid < off) {
            red[0][tid] += red[0][tid + off];
            red[1][tid] += red[1][tid + off];
        }
        __syncthreads();
    }
    if (tid == 0) {
        out[b * 2 + 0] = red[0][0] + fcb[0];
        out[b * 2 + 1] = red[1][0] + fcb[1];
    }
}

// ---------------- host launch sequence --------------------------------------
template <typename T>
static float* sym_addr(T& sym) {
    void* p = nullptr;
    cudaGetSymbolAddress(&p, sym);
    return (float*)p;
}

extern "C" void kernel_launch(void* const* d_in, const int* in_sizes, int n_in,
                              void* d_out, int out_size)
{
    const float* x          = (const float*)d_in[0];
    const float* w_ih_l0_f  = (const float*)d_in[1];
    const float* w_hh_l0_f  = (const float*)d_in[2];
    const float* b_ih_l0_f  = (const float*)d_in[3];
    const float* b_hh_l0_f  = (const float*)d_in[4];
    const float* w_ih_l0_r  = (const float*)d_in[5];
    const float* w_hh_l0_r  = (const float*)d_in[6];
    const float* b_ih_l0_r  = (const float*)d_in[7];
    const float* b_hh_l0_r  = (const float*)d_in[8];
    // d_in[9..12] = layer1 forward (dead code in reference: only hT_r is used)
    const float* w_ih_l1_r  = (const float*)d_in[13];
    const float* w_hh_l1_r  = (const float*)d_in[14];
    const float* b_ih_l1_r  = (const float*)d_in[15];
    const float* b_hh_l1_r  = (const float*)d_in[16];
    const float* fc1_w      = (const float*)d_in[17];
    const float* fc1_b      = (const float*)d_in[18];
    const float* fc_w       = (const float*)d_in[19];
    const float* fc_b       = (const float*)d_in[20];
    float* out = (float*)d_out;

    float* pre0f = sym_addr(PRE0F);
    float* pre0r = sym_addr(PRE0R);
    float* pre1  = pre0f;               // alias: PRE0F is dead once layer-0 recurrence ends
    float* out0  = sym_addr(OUT0);
    float* hbuf  = sym_addr(HBUF);
    const int slab = BSZ * HSZ;

    const int M = BSZ * SSZ;   // 32768

    // 1) init: lengths, ones states, barrier
    k_init<<<1536, 256>>>(x);

    // 2) layer-0 input projections (rows b*S+t -> stored [t][b][4H])
    dim3 gg(16, 256);
    k_gemm<<<gg, 256>>>(x, M, ESZ, w_ih_l0_f, b_ih_l0_f, b_hh_l0_f, pre0f, 1);
    k_gemm<<<gg, 256>>>(x, M, ESZ, w_ih_l0_r, b_ih_l0_r, b_hh_l0_r, pre0r, 1);

    // 3) layer-0 recurrence, both directions in one persistent kernel
    RP rp0;
    rp0.pre0 = pre0f; rp0.whh0 = w_hh_l0_f;
    rp0.h0a = hbuf + 0 * slab; rp0.h0b = hbuf + 1 * slab; rp0.c0 = hbuf + 2 * slab;
    rp0.out0 = out0;         rp0.rev0 = 0;
    rp0.pre1 = pre0r; rp0.whh1 = w_hh_l0_r;
    rp0.h1a = hbuf + 3 * slab; rp0.h1b = hbuf + 4 * slab; rp0.c1 = hbuf + 5 * slab;
    rp0.out1 = out0 + HSZ;   rp0.rev1 = 1;
    rp0.ndirs = 2;
    k_recur<<<NB_RECUR, 256>>>(rp0);

    // 4) layer-1 (reverse only) input projection: rows t*B+b already [t][b]
    k_gemm<<<gg, 256>>>(out0, M, 2 * HSZ, w_ih_l1_r, b_ih_l1_r, b_hh_l1_r, pre1, 0);

    // 5) layer-1 reverse recurrence
    k_reset<<<1, 1>>>();
    RP rp1;
    rp1.pre0 = pre1; rp1.whh0 = w_hh_l1_r;
    rp1.h0a = hbuf + 6 * slab; rp1.h0b = hbuf + 7 * slab; rp1.c0 = hbuf + 8 * slab;
    rp1.out0 = nullptr; rp1.rev0 = 1;
    rp1.pre1 = nullptr; rp1.whh1 = nullptr;
    rp1.h1a = nullptr; rp1.h1b = nullptr; rp1.c1 = nullptr;
    rp1.out1 = nullptr; rp1.rev1 = 0;
    rp1.ndirs = 1;
    k_recur<<<NB_RECUR, 256>>>(rp1);

    // 6) FC head; final h lives in buffer 'a' (S=256 even -> buf index 6)
    k_fc<<<BSZ, 256>>>(hbuf + 6 * slab, fc1_w, fc1_b, fc_w, fc_b, out);
}

// round 9
// speedup vs baseline: 1.5867x; 1.5867x over previous
#include <cuda_runtime.h>
#include <math.h>

// Problem constants
#define BSZ 128
#define SSZ 256
#define ESZ 300
#define HSZ 512
#define G4  2048           // 4*H
#define NB_RECUR 128       // persistent kernel grid (<= 148 SMs -> co-resident wave 1)

// ---------------- scratch (static device memory; no runtime allocation) -----
// PRE1 aliases PRE0F (l0-fwd pre fully consumed before l1 projection runs).
// All [t][r] tensors are stored in RANK-permuted batch order (r = rank).
__device__ float PRE0F[SSZ * BSZ * G4];          // [t][r][4H] l0 fwd  (later: l1 rev)
__device__ float PRE0R[SSZ * BSZ * G4];          // [t][r][4H] l0 rev
__device__ float OUT0 [SSZ * BSZ * 2 * HSZ];     // [t][r][2H] concat(fwd,rev)
__device__ float HBUF [9][BSZ * HSZ];            // h double-buffers (rank-permuted rows)
//  0,1: l0f h   3,4: l0r h   6,7: l1r h   (c lives in registers now)
__device__ int   LEN[BSZ];
__device__ int   RANK[BSZ];                      // original b -> rank (desc by length)
__device__ int   NACT[SSZ];                      // #rows with len > t
__device__ unsigned int BAR_CNT;
__device__ volatile unsigned int BAR_GEN;

__device__ __forceinline__ float sigm(float x) { return 1.0f / (1.0f + expf(-x)); }

// ---------------- init: lengths, ones-init h buffers, barrier reset ---------
__global__ void k_init(const float* __restrict__ x) {
    int tid = blockIdx.x * blockDim.x + threadIdx.x;
    const int slab = BSZ * HSZ;                   // 65536
    // ones-init the 3 "read-at-s0" h buffers: 0, 3, 6
    if (tid < 3 * slab) {
        int w = tid / slab, i = tid - w * slab;
        HBUF[w * 3][i] = 1.0f;
    }
    if (tid < BSZ) {
        int v = (int)x[((size_t)tid * SSZ + (SSZ - 1)) * ESZ];  // x[b, S-1, 0]
        LEN[tid] = v < SSZ ? v : SSZ;
    }
    if (tid == 0) { BAR_CNT = 0; BAR_GEN = 0; }
}

__global__ void k_reset() { BAR_CNT = 0; BAR_GEN = 0; }

// ---------------- prep: rank permutation (desc length, stable) + NACT -------
__global__ void k_prep() {
    __shared__ int sl[BSZ];
    int b = threadIdx.x;            // 128 threads
    sl[b] = LEN[b];
    __syncthreads();
    int mylen = sl[b];
    int rk = 0;
    for (int o = 0; o < BSZ; o++) {
        int lo = sl[o];
        rk += (lo > mylen) || (lo == mylen && o < b);
    }
    RANK[b] = rk;
    for (int t = b; t < SSZ; t += BSZ) {
        int c = 0;
        for (int o = 0; o < BSZ; o++) c += (sl[o] > t);
        NACT[t] = c;
    }
}

// ---------------- big NT-GEMM: C = A[M,K] * W[2048,K]^T + b1 + b2 -----------
// 128x128 block tile, 8x8 microtile, KC=8.
// mode 1: layer-0 projection. A rows = b*S+t. Output row = t*128 + RANK[b].
//         Row-activity: t < LEN[b]  (prefix within tile since tile = one b).
// mode 2: layer-1 projection. A rows = t*128 + r (already permuted).
//         Output row = m. Row-activity: r < NACT[t] (tile = one t).
__global__ void __launch_bounds__(256, 1) k_gemm(
    const float* __restrict__ A, int M, int K,
    const float* __restrict__ W,
    const float* __restrict__ b1, const float* __restrict__ b2,
    float* __restrict__ C, int mode)
{
    __shared__ float As[8][128];
    __shared__ float Bs[8][128];

    int tid = threadIdx.x;
    int ty = tid >> 4, tx = tid & 15;
    int mbase = blockIdx.y * 128;
    int nbase = blockIdx.x * 128;

    int rowlim = 128;
    if (mode == 1) {
        int b = mbase >> 8, t0 = mbase & 255;
        rowlim = LEN[b] - t0;
        if (rowlim > 128) rowlim = 128;
        if (rowlim <= 0) return;
    } else if (mode == 2) {
        int t = mbase >> 7;
        rowlim = NACT[t];
        if (rowlim <= 0) return;
    }
    bool act = (ty * 8) < rowlim;

    float acc[8][8];
#pragma unroll
    for (int i = 0; i < 8; i++)
#pragma unroll
        for (int j = 0; j < 8; j++) acc[i][j] = 0.0f;

    int lrow = tid >> 1;            // 0..127
    int lk   = (tid & 1) * 4;       // 0 or 4
    const float* Arow = A + (size_t)(mbase + lrow) * K;
    const float* Wrow = W + (size_t)(nbase + lrow) * K;

    for (int kb = 0; kb < K; kb += 8) {
        float av[4], wv[4];
        if (kb + lk + 3 < K) {
            float4 t = *(const float4*)(Arow + kb + lk);
            av[0] = t.x; av[1] = t.y; av[2] = t.z; av[3] = t.w;
            float4 u = *(const float4*)(Wrow + kb + lk);
            wv[0] = u.x; wv[1] = u.y; wv[2] = u.z; wv[3] = u.w;
        } else {
#pragma unroll
            for (int i = 0; i < 4; i++) {
                int k = kb + lk + i;
                av[i] = (k < K) ? Arow[k] : 0.0f;
                wv[i] = (k < K) ? Wrow[k] : 0.0f;
            }
        }
        __syncthreads();
#pragma unroll
        for (int i = 0; i < 4; i++) {
            As[lk + i][lrow] = av[i];
            Bs[lk + i][lrow] = wv[i];
        }
        __syncthreads();
        if (act) {
#pragma unroll
            for (int kk = 0; kk < 8; kk++) {
                float a[8], b[8];
                *(float4*)&a[0] = *(const float4*)&As[kk][ty * 8];
                *(float4*)&a[4] = *(const float4*)&As[kk][ty * 8 + 4];
                *(float4*)&b[0] = *(const float4*)&Bs[kk][tx * 8];
                *(float4*)&b[4] = *(const float4*)&Bs[kk][tx * 8 + 4];
#pragma unroll
                for (int i = 0; i < 8; i++)
#pragma unroll
                    for (int j = 0; j < 8; j++) acc[i][j] += a[i] * b[j];
            }
        }
    }

    // store with bias (active rows only)
#pragma unroll
    for (int i = 0; i < 8; i++) {
        int lr = ty * 8 + i;
        if (lr >= rowlim) continue;
        int m = mbase + lr;
        int crow = (mode == 1) ? (((m & 255) << 7) + RANK[m >> 8]) : m;
        float* Cr = C + (size_t)crow * G4 + nbase + tx * 8;
        const float* p1 = b1 + nbase + tx * 8;
        const float* p2 = b2 + nbase + tx * 8;
#pragma unroll
        for (int j = 0; j < 8; j++) Cr[j] = acc[i][j] + p1[j] + p2[j];
    }
}

// ---------------- grid-wide barrier -----------------------------------------
__device__ __forceinline__ void gsync(unsigned int& lg) {
    __syncthreads();
    if (threadIdx.x == 0) {
        __threadfence();
        unsigned int target = lg + 1;
        if (atomicAdd(&BAR_CNT, 1u) == (unsigned)(NB_RECUR - 1)) {
            atomicExch(&BAR_CNT, 0u);
            __threadfence();
            BAR_GEN = target;
        } else {
            while (BAR_GEN < target) __nanosleep(64);
        }
    }
    lg++;
    __syncthreads();
}

// ---------------- persistent recurrence kernel ------------------------------
// Block = (direction, NC hidden cols). W_hh tile resident in smem for all 256
// steps (k-major, [512][NC*4+4]); wrow order wl = jj*4 + g so each thread's
// accumulators are the 4 gates of one (row, col) cell -> gate math register-
// local; c and own-h live in registers for the whole scan. h exchanged via
// rank-permuted global double-buffer; 1 grid sync per step. Rows are sorted by
// descending length: row r active at t iff r < NACT[t] -> warp-granular skip.
struct RQ {
    const float* pre[2];
    const float* whh[2];
    float* ha[2];
    float* hb[2];
    float* outp[2];     // pre-offset by dir*512; nullptr = no output
    int rev[2];
};

template <int NC, int RPT>
__global__ void __launch_bounds__(256, 1) k_recur2(RQ p) {
    extern __shared__ float sm[];
    const int WS = NC * 4 + 4;           // padded wrow stride (floats)
    float* ws = sm;                      // [512][WS]
    float* hs = sm + 512 * WS;           // [64][128]  k-major h chunk

    int tid = threadIdx.x;
    const int bpd = (NC == 8) ? 64 : 128;     // blocks per direction
    int dir = blockIdx.x / bpd;
    int j0  = (blockIdx.x % bpd) * NC;

    const float* whh = p.whh[dir];
    const float* pre = p.pre[dir];
    float* ha = p.ha[dir];
    float* hb = p.hb[dir];
    float* outp = p.outp[dir];
    int rev = p.rev[dir];

    // one-time W tile load: ws[k][wl], wl = jj*4 + g, global wrow = g*512+j0+jj
    for (int idx = tid; idx < 512 * NC * 4; idx += 256) {
        int k  = idx & 511;
        int wl = idx >> 9;
        int jj = wl >> 2, g = wl & 3;
        ws[k * WS + wl] = whh[((size_t)(g * 512 + j0 + jj)) * 512 + k];
    }

    int tx = tid & (NC - 1);
    int ty = tid >> ((NC == 8) ? 3 : 2);
    int jg = j0 + tx;
    int r0 = ty * RPT;
    int rstage = tid & 127;
    int half = tid >> 7;

    float hreg[RPT], creg[RPT];
#pragma unroll
    for (int i = 0; i < RPT; i++) { hreg[i] = 1.0f; creg[i] = 1.0f; }

    unsigned int lg = 0;

    for (int s = 0; s < SSZ; s++) {
        int tt = rev ? (SSZ - 1 - s) : s;
        int nact = NACT[tt];
        const float* hin = (s & 1) ? hb : ha;
        float* hout      = (s & 1) ? ha : hb;

        float acc[RPT][4];
#pragma unroll
        for (int i = 0; i < RPT; i++) {
            acc[i][0] = 0.f; acc[i][1] = 0.f; acc[i][2] = 0.f; acc[i][3] = 0.f;
        }
        bool act_gemm = (r0 < nact);

        for (int kb = 0; kb < HSZ; kb += 64) {
            __syncthreads();            // hs free from previous chunk
            if (rstage < nact) {
                const float4* src = (const float4*)(hin + (size_t)rstage * HSZ + kb);
#pragma unroll
                for (int q = 0; q < 8; q++) {
                    int qi = half * 8 + q;
                    float4 v = src[qi];
                    hs[(qi * 4 + 0) * 128 + rstage] = v.x;
                    hs[(qi * 4 + 1) * 128 + rstage] = v.y;
                    hs[(qi * 4 + 2) * 128 + rstage] = v.z;
                    hs[(qi * 4 + 3) * 128 + rstage] = v.w;
                }
            }
            __syncthreads();
            if (act_gemm) {
#pragma unroll 16
                for (int kk = 0; kk < 64; kk++) {
                    float4 bv = *(const float4*)(ws + (kb + kk) * WS + tx * 4);
                    if (RPT == 4) {
                        float4 av = *(const float4*)(hs + kk * 128 + r0);
                        acc[0][0] += av.x * bv.x; acc[0][1] += av.x * bv.y;
                        acc[0][2] += av.x * bv.z; acc[0][3] += av.x * bv.w;
                        acc[1][0] += av.y * bv.x; acc[1][1] += av.y * bv.y;
                        acc[1][2] += av.y * bv.z; acc[1][3] += av.y * bv.w;
                        acc[2][0] += av.z * bv.x; acc[2][1] += av.z * bv.y;
                        acc[2][2] += av.z * bv.z; acc[2][3] += av.z * bv.w;
                        acc[3][0] += av.w * bv.x; acc[3][1] += av.w * bv.y;
                        acc[3][2] += av.w * bv.z; acc[3][3] += av.w * bv.w;
                    } else {
                        float2 av = *(const float2*)(hs + kk * 128 + r0);
                        acc[0][0] += av.x * bv.x; acc[0][1] += av.x * bv.y;
                        acc[0][2] += av.x * bv.z; acc[0][3] += av.x * bv.w;
                        acc[1][0] += av.y * bv.x; acc[1][1] += av.y * bv.y;
                        acc[1][2] += av.y * bv.z; acc[1][3] += av.y * bv.w;
                    }
                }
            }
        }

        // gates: acc[i][g] are the 4 gates of cell (r0+i, jg); c/h in registers
#pragma unroll
        for (int i = 0; i < RPT; i++) {
            int r = r0 + i;
            if (r < nact) {
                const float* pb = pre + ((size_t)tt * BSZ + r) * G4 + jg;
                float zi = acc[i][0] + pb[0];
                float zf = acc[i][1] + pb[512];
                float zg = acc[i][2] + pb[1024];
                float zo = acc[i][3] + pb[1536];
                float cn = sigm(zf) * creg[i] + sigm(zi) * tanhf(zg);
                creg[i] = cn;
                hreg[i] = sigm(zo) * tanhf(cn);
            }
            hout[(size_t)r * HSZ + jg] = hreg[i];
            if (outp) outp[((size_t)tt * BSZ + r) * (2 * HSZ) + jg] = hreg[i];
        }
        gsync(lg);
    }
}

// ---------------- final FC head: out = (h@fc1^T + b1) @ fc^T + b ------------
__global__ void k_fc(const float* __restrict__ h,
                     const float* __restrict__ fc1w, const float* __restrict__ fc1b,
                     const float* __restrict__ fcw,  const float* __restrict__ fcb,
                     float* __restrict__ out)
{
    __shared__ float tmp[HSZ];
    __shared__ float red[2][256];
    int b = blockIdx.x, tid = threadIdx.x;
    const float* hb = h + (size_t)RANK[b] * HSZ;   // rank-permuted h rows

    for (int j = tid; j < HSZ; j += 256) {
        const float* w = fc1w + (size_t)j * HSZ;
        float s0 = 0.f, s1 = 0.f, s2 = 0.f, s3 = 0.f;
        for (int k = 0; k < HSZ; k += 4) {
            s0 += hb[k] * w[k];         s1 += hb[k + 1] * w[k + 1];
            s2 += hb[k + 2] * w[k + 2]; s3 += hb[k + 3] * w[k + 3];
        }
        tmp[j] = s0 + s1 + s2 + s3 + fc1b[j];
    }
    __syncthreads();
    float p0 = 0.f, p1 = 0.f;
    for (int k = tid; k < HSZ; k += 256) {
        p0 += tmp[k] * fcw[k];
        p1 += tmp[k] * fcw[HSZ + k];
    }
    red[0][tid] = p0; red[1][tid] = p1;
    __syncthreads();
    for (int off = 128; off > 0; off >>= 1) {
        if (tid < off) {
            red[0][tid] += red[0][tid + off];
            red[1][tid] += red[1][tid + off];
        }
        __syncthreads();
    }
    if (tid == 0) {
        out[b * 2 + 0] = red[0][0] + fcb[0];
        out[b * 2 + 1] = red[1][0] + fcb[1];
    }
}

// ---------------- host launch sequence --------------------------------------
template <typename T>
static float* sym_addr(T& sym) {
    void* p = nullptr;
    cudaGetSymbolAddress(&p, sym);
    return (float*)p;
}

extern "C" void kernel_launch(void* const* d_in, const int* in_sizes, int n_in,
                              void* d_out, int out_size)
{
    const float* x          = (const float*)d_in[0];
    const float* w_ih_l0_f  = (const float*)d_in[1];
    const float* w_hh_l0_f  = (const float*)d_in[2];
    const float* b_ih_l0_f  = (const float*)d_in[3];
    const float* b_hh_l0_f  = (const float*)d_in[4];
    const float* w_ih_l0_r  = (const float*)d_in[5];
    const float* w_hh_l0_r  = (const float*)d_in[6];
    const float* b_ih_l0_r  = (const float*)d_in[7];
    const float* b_hh_l0_r  = (const float*)d_in[8];
    // d_in[9..12] = layer-1 forward (dead code in reference: only hT_r is used)
    const float* w_ih_l1_r  = (const float*)d_in[13];
    const float* w_hh_l1_r  = (const float*)d_in[14];
    const float* b_ih_l1_r  = (const float*)d_in[15];
    const float* b_hh_l1_r  = (const float*)d_in[16];
    const float* fc1_w      = (const float*)d_in[17];
    const float* fc1_b      = (const float*)d_in[18];
    const float* fc_w       = (const float*)d_in[19];
    const float* fc_b       = (const float*)d_in[20];
    float* out = (float*)d_out;

    float* pre0f = sym_addr(PRE0F);
    float* pre0r = sym_addr(PRE0R);
    float* pre1  = pre0f;               // alias: PRE0F dead after layer-0 recurrence
    float* out0  = sym_addr(OUT0);
    float* hbuf  = sym_addr(HBUF);
    const int slab = BSZ * HSZ;
    const int M = BSZ * SSZ;            // 32768

    // dynamic-smem opt-in for the persistent recurrence kernels
    const int SM8 = (512 * (8 * 4 + 4) + 64 * 128) * 4;   // 106496 B
    const int SM4 = (512 * (4 * 4 + 4) + 64 * 128) * 4;   //  73728 B
    cudaFuncSetAttribute(k_recur2<8, 4>, cudaFuncAttributeMaxDynamicSharedMemorySize, SM8);
    cudaFuncSetAttribute(k_recur2<4, 2>, cudaFuncAttributeMaxDynamicSharedMemorySize, SM4);

    // 1) init + rank/NACT prep
    k_init<<<768, 256>>>(x);
    k_prep<<<1, BSZ>>>();

    // 2) layer-0 input projections (rows b*S+t -> stored [t][rank][4H], row-skip)
    dim3 gg(16, 256);
    k_gemm<<<gg, 256>>>(x, M, ESZ, w_ih_l0_f, b_ih_l0_f, b_hh_l0_f, pre0f, 1);
    k_gemm<<<gg, 256>>>(x, M, ESZ, w_ih_l0_r, b_ih_l0_r, b_hh_l0_r, pre0r, 1);

    // 3) layer-0 recurrence: both directions, 128 persistent blocks
    RQ rq0;
    rq0.pre[0] = pre0f; rq0.whh[0] = w_hh_l0_f;
    rq0.ha[0] = hbuf + 0 * slab; rq0.hb[0] = hbuf + 1 * slab;
    rq0.outp[0] = out0;           rq0.rev[0] = 0;
    rq0.pre[1] = pre0r; rq0.whh[1] = w_hh_l0_r;
    rq0.ha[1] = hbuf + 3 * slab; rq0.hb[1] = hbuf + 4 * slab;
    rq0.outp[1] = out0 + HSZ;     rq0.rev[1] = 1;
    k_recur2<8, 4><<<NB_RECUR, 256, SM8>>>(rq0);

    // 4) layer-1 (reverse only) input projection: rows [t][rank], row-skip by NACT
    k_gemm<<<gg, 256>>>(out0, M, 2 * HSZ, w_ih_l1_r, b_ih_l1_r, b_hh_l1_r, pre1, 2);

    // 5) layer-1 reverse recurrence: 128 blocks of 4 cols each
    k_reset<<<1, 1>>>();
    RQ rq1;
    rq1.pre[0] = pre1; rq1.whh[0] = w_hh_l1_r;
    rq1.ha[0] = hbuf + 6 * slab; rq1.hb[0] = hbuf + 7 * slab;
    rq1.outp[0] = nullptr;        rq1.rev[0] = 1;
    rq1.pre[1] = nullptr; rq1.whh[1] = nullptr;
    rq1.ha[1] = nullptr; rq1.hb[1] = nullptr;
    rq1.outp[1] = nullptr;        rq1.rev[1] = 0;
    k_recur2<4, 2><<<NB_RECUR, 256, SM4>>>(rq1);

    // 6) FC head; final h (s=255 -> hout = ha = buf 6), rank-indirected
    k_fc<<<BSZ, 256>>>(hbuf + 6 * slab, fc1_w, fc1_b, fc_w, fc_b, out);
}